// round 3
// baseline (speedup 1.0000x reference)
#include <cuda_runtime.h>
#include <cuda_bf16.h>

// Problem constants (shapes fixed by the dataset; guarded at launch).
#define NMAX 100352          // >= N=100000, padded
#define CUTOFF   0.9f
#define CUT2     (CUTOFF * CUTOFF)
#define PREFAC   138.93544539709032f

// Static device scratch (allocation-free rule: __device__ globals are the
// sanctioned mechanism).
__device__ float4 g_pos[NMAX];   // x, y, z, charge
__device__ float4 g_par[NMAX];   // sigma, sqrt(eps), group_id(float), pad
__device__ double g_acc;

// ---------------------------------------------------------------------------
// Pack kernel: build gather-friendly 16B records; also zero the accumulator.
// ---------------------------------------------------------------------------
__global__ void nb_pack_kernel(const float* __restrict__ coords,
                               const float* __restrict__ charges,
                               const float* __restrict__ sigma,
                               const float* __restrict__ epsilon,
                               int n)
{
    int i = blockIdx.x * blockDim.x + threadIdx.x;
    if (i == 0) g_acc = 0.0;
    if (i < n) {
        g_pos[i] = make_float4(coords[3 * i + 0],
                               coords[3 * i + 1],
                               coords[3 * i + 2],
                               charges[i]);
        g_par[i] = make_float4(sigma[i],
                               sqrtf(epsilon[i]),
                               (float)(i / 3),   // molecule/group id (< 2^24, exact)
                               0.0f);
    }
}

// ---------------------------------------------------------------------------
// Hot-path helpers
// ---------------------------------------------------------------------------
// Minimum-image squared distance. For |d| < L this equals
// (d - L*round(d/L))^2 component-wise: min(|d|, L-|d|)^2.
__device__ __forceinline__ float min_image_r2(const float4 a, const float4 b,
                                              float Lx, float Ly, float Lz)
{
    float dx = fabsf(a.x - b.x); dx = fminf(dx, Lx - dx);
    float dy = fabsf(a.y - b.y); dy = fminf(dy, Ly - dy);
    float dz = fabsf(a.z - b.z); dz = fminf(dz, Lz - dz);
    return fmaf(dx, dx, fmaf(dy, dy, dz * dz));
}

// Rare path: full Coulomb + LJ for a pair already known to satisfy r2 < CUT2.
// Gathers the parameter table and applies the molecule-exclusion here
// (i/3 == j/3 implies i == j is also covered).
__device__ __forceinline__ float pair_energy(int i, int j,
                                             float qi, float qj, float r2)
{
    float4 pa = __ldg(&g_par[i]);
    float4 pb = __ldg(&g_par[j]);
    if (pa.z == pb.z) return 0.0f;          // same molecule (or i==j)

    float inv_r = rsqrtf(r2);
    // one Newton step: y *= (1.5 - 0.5*x*y*y)  — cheap, rare path only
    inv_r = inv_r * fmaf(-0.5f * r2 * inv_r, inv_r, 1.5f);

    float e_coul = PREFAC * qi * qj * inv_r;

    float sig  = 0.5f * (pa.x + pb.x);
    float eps  = pa.y * pb.y;               // sqrt(ei)*sqrt(ej) = sqrt(ei*ej)
    float ir2  = inv_r * inv_r;
    float sr2  = sig * sig * ir2;
    float sr6  = sr2 * sr2 * sr2;
    float e_lj = 4.0f * eps * (sr6 * sr6 - sr6);

    return e_coul + e_lj;
}

// ---------------------------------------------------------------------------
// Main pair kernel: grid-stride over int4 units (2 pairs per unit).
// ---------------------------------------------------------------------------
__global__ __launch_bounds__(256)
void nb_pair_kernel(const int4* __restrict__ pairs4,
                    long long nUnits,
                    int nPairs,
                    const float* __restrict__ box)
{
    const float Lx = __ldg(&box[0]);
    const float Ly = __ldg(&box[4]);
    const float Lz = __ldg(&box[8]);

    double acc = 0.0;

    const long long stride = (long long)gridDim.x * blockDim.x;
    for (long long u = (long long)blockIdx.x * blockDim.x + threadIdx.x;
         u < nUnits; u += stride)
    {
        const int4 p = __ldg(&pairs4[u]);

        // Issue all four gathers up front for MLP.
        const float4 a0 = __ldg(&g_pos[p.x]);
        const float4 b0 = __ldg(&g_pos[p.y]);
        const float4 a1 = __ldg(&g_pos[p.z]);
        const float4 b1 = __ldg(&g_pos[p.w]);

        const float r2a = min_image_r2(a0, b0, Lx, Ly, Lz);
        const float r2b = min_image_r2(a1, b1, Lx, Ly, Lz);

        const bool va = r2a < CUT2;
        const bool vb = r2b < CUT2;
        if (va | vb) {                       // rare (~0.6% of units)
            if (va) acc += (double)pair_energy(p.x, p.y, a0.w, b0.w, r2a);
            if (vb) acc += (double)pair_energy(p.z, p.w, a1.w, b1.w, r2b);
        }
    }

    // Odd-pair tail (not hit for the dataset's 16M pairs, kept for safety).
    if ((nPairs & 1) && blockIdx.x == 0 && threadIdx.x == 0) {
        const int2* p2 = (const int2*)pairs4;
        const int2 p = p2[nPairs - 1];
        const float4 a = __ldg(&g_pos[p.x]);
        const float4 b = __ldg(&g_pos[p.y]);
        const float r2 = min_image_r2(a, b, Lx, Ly, Lz);
        if (r2 < CUT2)
            acc += (double)pair_energy(p.x, p.y, a.w, b.w, r2);
    }

    // Warp reduction, then one double atomic per warp with nonzero sum.
    #pragma unroll
    for (int o = 16; o > 0; o >>= 1)
        acc += __shfl_xor_sync(0xffffffffu, acc, o);
    if ((threadIdx.x & 31) == 0 && acc != 0.0)
        atomicAdd(&g_acc, acc);
}

// ---------------------------------------------------------------------------
// Finish: cast the double accumulator to the float output.
// ---------------------------------------------------------------------------
__global__ void nb_finish_kernel(float* __restrict__ out)
{
    if (threadIdx.x == 0) out[0] = (float)g_acc;
}

// ---------------------------------------------------------------------------
// Launch. Input order per metadata: coords, box, charges, sigma, epsilon, pairs.
// ---------------------------------------------------------------------------
extern "C" void kernel_launch(void* const* d_in, const int* in_sizes, int n_in,
                              void* d_out, int out_size)
{
    const float* coords  = (const float*)d_in[0];
    const float* box     = (const float*)d_in[1];
    const float* charges = (const float*)d_in[2];
    const float* sigma   = (const float*)d_in[3];
    const float* epsilon = (const float*)d_in[4];
    const int*   pairs   = (const int*)d_in[5];

    const int n       = in_sizes[0] / 3;        // 100000
    const int nPairs  = in_sizes[5] / 2;        // 16000000
    const long long nUnits = nPairs / 2;        // int4 units (2 pairs each)

    nb_pack_kernel<<<(n + 255) / 256, 256>>>(coords, charges, sigma, epsilon, n);
    nb_pair_kernel<<<2048, 256>>>((const int4*)pairs, nUnits, nPairs, box);
    nb_finish_kernel<<<1, 32>>>((float*)d_out);
}